// round 6
// baseline (speedup 1.0000x reference)
#include <cuda_runtime.h>

// out = relu(cos(x+theta) @ W1 + b1) @ W2 + b2
// x: [B*S, 8] fp32, W1: [8,32], W2: [32,8], out: [B*S, 8] fp32
//
// f32x2-packed (2 rows/lane, 4 rows/thread), layers fused in groups of 4
// hidden columns. Occupancy push: __launch_bounds__(128,6), no xr staging,
// layer-2 weights (4x LDS.128 covering all 8 outputs) prefetched before relu.

using u64 = unsigned long long;

__device__ __forceinline__ u64 pack2(float lo, float hi) {
    u64 r;
    asm("mov.b64 %0, {%1, %2};" : "=l"(r) : "f"(lo), "f"(hi));
    return r;
}

__device__ __forceinline__ float2 unpack2(u64 v) {
    float2 f;
    asm("mov.b64 {%0, %1}, %2;" : "=f"(f.x), "=f"(f.y) : "l"(v));
    return f;
}

__device__ __forceinline__ u64 ffma2(u64 a, u64 b, u64 c) {
    u64 d;
    asm("fma.rn.f32x2 %0, %1, %2, %3;" : "=l"(d) : "l"(a), "l"(b), "l"(c));
    return d;
}

__device__ __forceinline__ u64 relu2(u64 v) {
    float2 f = unpack2(v);
    f.x = fmaxf(f.x, 0.0f);
    f.y = fmaxf(f.y, 0.0f);
    return pack2(f.x, f.y);
}

constexpr int E = 8;
constexpr int F = 32;
constexpr int JG = 4;
constexpr int PAIRS = 2;
constexpr int ROWS_PER_THREAD = 2 * PAIRS;
constexpr int BLOCK = 128;

__global__ __launch_bounds__(BLOCK, 6)
void ffq_kernel(const float* __restrict__ x,
                const float* __restrict__ theta,
                const float* __restrict__ w1,
                const float* __restrict__ b1,
                const float* __restrict__ w2,
                const float* __restrict__ b2,
                float* __restrict__ out,
                long nrows)
{
    __shared__ __align__(16) u64 s_w1t[F * E];
    __shared__ __align__(16) u64 s_w2 [F * E];
    __shared__ __align__(16) u64 s_b1 [F];
    __shared__ __align__(16) u64 s_b2 [E];
    __shared__ float s_th[E];

    const int t = threadIdx.x;

    for (int k = t; k < F * E; k += BLOCK) {
        int j = k / E, i = k % E;
        float a = w1[i * F + j];
        s_w1t[k] = pack2(a, a);
        float b = w2[k];                   // w2 is [F][E]; k = j*E+e
        s_w2[k] = pack2(b, b);
    }
    if (t < F) { float v = b1[t]; s_b1[t] = pack2(v, v); }
    if (t < E) {
        float v = b2[t]; s_b2[t] = pack2(v, v);
        s_th[t] = theta[t];
    }
    __syncthreads();

    const long row0 = ((long)blockIdx.x * BLOCK + t) * ROWS_PER_THREAD;
    if (row0 >= nrows) return;

    const float4* xv = (const float4*)(x + row0 * E);
    float4 xa0 = xv[0], xb0 = xv[1];
    float4 xa1 = xv[2], xb1 = xv[3];
    float4 xa2 = xv[4], xb2 = xv[5];
    float4 xa3 = xv[6], xb3 = xv[7];

    float th[E];
#pragma unroll
    for (int i = 0; i < E; i++) th[i] = s_th[i];

    u64 q[PAIRS][E];
    q[0][0] = pack2(__cosf(xa0.x + th[0]), __cosf(xa1.x + th[0]));
    q[0][1] = pack2(__cosf(xa0.y + th[1]), __cosf(xa1.y + th[1]));
    q[0][2] = pack2(__cosf(xa0.z + th[2]), __cosf(xa1.z + th[2]));
    q[0][3] = pack2(__cosf(xa0.w + th[3]), __cosf(xa1.w + th[3]));
    q[0][4] = pack2(__cosf(xb0.x + th[4]), __cosf(xb1.x + th[4]));
    q[0][5] = pack2(__cosf(xb0.y + th[5]), __cosf(xb1.y + th[5]));
    q[0][6] = pack2(__cosf(xb0.z + th[6]), __cosf(xb1.z + th[6]));
    q[0][7] = pack2(__cosf(xb0.w + th[7]), __cosf(xb1.w + th[7]));
    q[1][0] = pack2(__cosf(xa2.x + th[0]), __cosf(xa3.x + th[0]));
    q[1][1] = pack2(__cosf(xa2.y + th[1]), __cosf(xa3.y + th[1]));
    q[1][2] = pack2(__cosf(xa2.z + th[2]), __cosf(xa3.z + th[2]));
    q[1][3] = pack2(__cosf(xa2.w + th[3]), __cosf(xa3.w + th[3]));
    q[1][4] = pack2(__cosf(xb2.x + th[4]), __cosf(xb3.x + th[4]));
    q[1][5] = pack2(__cosf(xb2.y + th[5]), __cosf(xb3.y + th[5]));
    q[1][6] = pack2(__cosf(xb2.z + th[6]), __cosf(xb3.z + th[6]));
    q[1][7] = pack2(__cosf(xb2.w + th[7]), __cosf(xb3.w + th[7]));

    u64 o[PAIRS][E];
#pragma unroll
    for (int e = 0; e < E; e++) {
        u64 be = s_b2[e];
        o[0][e] = be;
        o[1][e] = be;
    }

#pragma unroll
    for (int jg = 0; jg < F / JG; jg++) {
        const int j0 = jg * JG;

        const ulonglong2* bb = (const ulonglong2*)&s_b1[j0];
        ulonglong2 bv0 = bb[0];
        ulonglong2 bv1 = bb[1];

        u64 h[JG][PAIRS];
        h[0][0] = bv0.x; h[0][1] = bv0.x;
        h[1][0] = bv0.y; h[1][1] = bv0.y;
        h[2][0] = bv1.x; h[2][1] = bv1.x;
        h[3][0] = bv1.y; h[3][1] = bv1.y;

#pragma unroll
        for (int jj = 0; jj < JG; jj++) {
            const ulonglong2* wc = (const ulonglong2*)&s_w1t[(j0 + jj) * E];
#pragma unroll
            for (int i2 = 0; i2 < E / 2; i2++) {
                ulonglong2 w = wc[i2];
                h[jj][0] = ffma2(q[0][2 * i2 + 0], w.x, h[jj][0]);
                h[jj][1] = ffma2(q[1][2 * i2 + 0], w.x, h[jj][1]);
                h[jj][0] = ffma2(q[0][2 * i2 + 1], w.y, h[jj][0]);
                h[jj][1] = ffma2(q[1][2 * i2 + 1], w.y, h[jj][1]);
            }
        }

#pragma unroll
        for (int jj = 0; jj < JG; jj++) {
            h[jj][0] = relu2(h[jj][0]);
            h[jj][1] = relu2(h[jj][1]);
        }

        // layer 2: per column jj, 4x LDS.128 covering e=0..7
#pragma unroll
        for (int jj = 0; jj < JG; jj++) {
            const ulonglong2* wp = (const ulonglong2*)&s_w2[(j0 + jj) * E];
#pragma unroll
            for (int e2 = 0; e2 < E / 2; e2++) {
                ulonglong2 w = wp[e2];
                o[0][2 * e2 + 0] = ffma2(h[jj][0], w.x, o[0][2 * e2 + 0]);
                o[1][2 * e2 + 0] = ffma2(h[jj][1], w.x, o[1][2 * e2 + 0]);
                o[0][2 * e2 + 1] = ffma2(h[jj][0], w.y, o[0][2 * e2 + 1]);
                o[1][2 * e2 + 1] = ffma2(h[jj][1], w.y, o[1][2 * e2 + 1]);
            }
        }
    }

    float4* ov = (float4*)(out + row0 * E);
#pragma unroll
    for (int p = 0; p < PAIRS; p++) {
        float2 f[E];
#pragma unroll
        for (int e = 0; e < E; e++) f[e] = unpack2(o[p][e]);
        ov[4 * p + 0] = make_float4(f[0].x, f[1].x, f[2].x, f[3].x);
        ov[4 * p + 1] = make_float4(f[4].x, f[5].x, f[6].x, f[7].x);
        ov[4 * p + 2] = make_float4(f[0].y, f[1].y, f[2].y, f[3].y);
        ov[4 * p + 3] = make_float4(f[4].y, f[5].y, f[6].y, f[7].y);
    }
}

extern "C" void kernel_launch(void* const* d_in, const int* in_sizes, int n_in,
                              void* d_out, int out_size)
{
    const float* x     = (const float*)d_in[0];
    const float* theta = (const float*)d_in[1];
    const float* w1    = (const float*)d_in[2];
    const float* b1    = (const float*)d_in[3];
    const float* w2    = (const float*)d_in[4];
    const float* b2    = (const float*)d_in[5];
    float* out = (float*)d_out;

    const long nrows = (long)in_sizes[0] / E;  // 524288
    const long nthreads = (nrows + ROWS_PER_THREAD - 1) / ROWS_PER_THREAD;
    const int grid = (int)((nthreads + BLOCK - 1) / BLOCK);

    ffq_kernel<<<grid, BLOCK>>>(x, theta, w1, b1, w2, b2, out, nrows);
}

// round 7
// speedup vs baseline: 1.0792x; 1.0792x over previous
#include <cuda_runtime.h>

// out = relu(cos(x+theta) @ W1 + b1) @ W2 + b2
// x: [B*S, 8] fp32, W1: [8,32], W2: [32,8], out: [B*S, 8] fp32
//
// f32x2-packed, 2 rows/thread (ONE pair) to halve per-thread live state and
// double warp count vs R4 (same per-warp instruction mix, 2x latency hiding).
// Hidden dim processed in groups of 8 columns: 8 independent layer-1 chains,
// 8 layer-2 accumulator chains. Weights {w,w}-broadcast in shared, LDS.128.

using u64 = unsigned long long;

__device__ __forceinline__ u64 pack2(float lo, float hi) {
    u64 r;
    asm("mov.b64 %0, {%1, %2};" : "=l"(r) : "f"(lo), "f"(hi));
    return r;
}

__device__ __forceinline__ float2 unpack2(u64 v) {
    float2 f;
    asm("mov.b64 {%0, %1}, %2;" : "=f"(f.x), "=f"(f.y) : "l"(v));
    return f;
}

__device__ __forceinline__ u64 ffma2(u64 a, u64 b, u64 c) {
    u64 d;
    asm("fma.rn.f32x2 %0, %1, %2, %3;" : "=l"(d) : "l"(a), "l"(b), "l"(c));
    return d;
}

__device__ __forceinline__ u64 relu2(u64 v) {
    float2 f = unpack2(v);
    f.x = fmaxf(f.x, 0.0f);
    f.y = fmaxf(f.y, 0.0f);
    return pack2(f.x, f.y);
}

constexpr int E = 8;
constexpr int F = 32;
constexpr int JG = 8;                 // hidden columns per fused group
constexpr int ROWS_PER_THREAD = 2;    // one f32x2 pair
constexpr int BLOCK = 128;

__global__ __launch_bounds__(BLOCK)
void ffq_kernel(const float* __restrict__ x,
                const float* __restrict__ theta,
                const float* __restrict__ w1,
                const float* __restrict__ b1,
                const float* __restrict__ w2,
                const float* __restrict__ b2,
                float* __restrict__ out,
                long nrows)
{
    // s_w1t[j*E + i] = {w1[i][j], w1[i][j]}  (column j contiguous, 16B-aligned)
    // s_w2 [j*E + e] = {w2[j][e], w2[j][e]}  (row j contiguous)
    __shared__ __align__(16) u64 s_w1t[F * E];
    __shared__ __align__(16) u64 s_w2 [F * E];
    __shared__ __align__(16) u64 s_b1 [F];
    __shared__ __align__(16) u64 s_b2 [E];
    __shared__ float s_th[E];

    const int t = threadIdx.x;

    for (int k = t; k < F * E; k += BLOCK) {
        int j = k / E, i = k % E;
        float a = w1[i * F + j];
        s_w1t[k] = pack2(a, a);
        float b = w2[k];                   // w2 is [F][E]; k = j*E+e
        s_w2[k] = pack2(b, b);
    }
    if (t < F) { float v = b1[t]; s_b1[t] = pack2(v, v); }
    if (t < E) {
        float v = b2[t]; s_b2[t] = pack2(v, v);
        s_th[t] = theta[t];
    }
    __syncthreads();

    const long row0 = ((long)blockIdx.x * BLOCK + t) * ROWS_PER_THREAD;
    if (row0 >= nrows) return;

    // ---- Load 2 rows of x (4x LDG.128), fold straight into q = cos(x+theta)
    const float4* xv = (const float4*)(x + row0 * E);
    float4 xa0 = xv[0], xb0 = xv[1];   // row 0
    float4 xa1 = xv[2], xb1 = xv[3];   // row 1

    float th[E];
#pragma unroll
    for (int i = 0; i < E; i++) th[i] = s_th[i];

    u64 q[E];   // {row0, row1}
    q[0] = pack2(__cosf(xa0.x + th[0]), __cosf(xa1.x + th[0]));
    q[1] = pack2(__cosf(xa0.y + th[1]), __cosf(xa1.y + th[1]));
    q[2] = pack2(__cosf(xa0.z + th[2]), __cosf(xa1.z + th[2]));
    q[3] = pack2(__cosf(xa0.w + th[3]), __cosf(xa1.w + th[3]));
    q[4] = pack2(__cosf(xb0.x + th[4]), __cosf(xb1.x + th[4]));
    q[5] = pack2(__cosf(xb0.y + th[5]), __cosf(xb1.y + th[5]));
    q[6] = pack2(__cosf(xb0.z + th[6]), __cosf(xb1.z + th[6]));
    q[7] = pack2(__cosf(xb0.w + th[7]), __cosf(xb1.w + th[7]));

    // ---- Output accumulators, init with b2
    u64 o[E];
#pragma unroll
    for (int e = 0; e < E; e++) o[e] = s_b2[e];

    // ---- Fused layers in groups of JG=8 hidden columns
#pragma unroll
    for (int jg = 0; jg < F / JG; jg++) {
        const int j0 = jg * JG;

        // biases for the 8 columns: 4x LDS.128
        u64 h[JG];
        {
            const ulonglong2* bb = (const ulonglong2*)&s_b1[j0];
#pragma unroll
            for (int jj2 = 0; jj2 < JG / 2; jj2++) {
                ulonglong2 bv = bb[jj2];
                h[2 * jj2 + 0] = bv.x;
                h[2 * jj2 + 1] = bv.y;
            }
        }

        // layer 1: 8 independent chains, weights via LDS.128
#pragma unroll
        for (int jj = 0; jj < JG; jj++) {
            const ulonglong2* wc = (const ulonglong2*)&s_w1t[(j0 + jj) * E];
#pragma unroll
            for (int i2 = 0; i2 < E / 2; i2++) {
                ulonglong2 w = wc[i2];
                h[jj] = ffma2(q[2 * i2 + 0], w.x, h[jj]);
                h[jj] = ffma2(q[2 * i2 + 1], w.y, h[jj]);
            }
        }

#pragma unroll
        for (int jj = 0; jj < JG; jj++) h[jj] = relu2(h[jj]);

        // layer 2: accumulate into 8 independent o chains
#pragma unroll
        for (int jj = 0; jj < JG; jj++) {
            const ulonglong2* wp = (const ulonglong2*)&s_w2[(j0 + jj) * E];
#pragma unroll
            for (int e2 = 0; e2 < E / 2; e2++) {
                ulonglong2 w = wp[e2];
                o[2 * e2 + 0] = ffma2(h[jj], w.x, o[2 * e2 + 0]);
                o[2 * e2 + 1] = ffma2(h[jj], w.y, o[2 * e2 + 1]);
            }
        }
    }

    // ---- Store 2 rows (4x STG.128): row0 = lo halves, row1 = hi halves
    float4* ov = (float4*)(out + row0 * E);
    float2 f[E];
#pragma unroll
    for (int e = 0; e < E; e++) f[e] = unpack2(o[e]);
    ov[0] = make_float4(f[0].x, f[1].x, f[2].x, f[3].x);
    ov[1] = make_float4(f[4].x, f[5].x, f[6].x, f[7].x);
    ov[2] = make_float4(f[0].y, f[1].y, f[2].y, f[3].y);
    ov[3] = make_float4(f[4].y, f[5].y, f[6].y, f[7].y);
}

extern "C" void kernel_launch(void* const* d_in, const int* in_sizes, int n_in,
                              void* d_out, int out_size)
{
    const float* x     = (const float*)d_in[0];
    const float* theta = (const float*)d_in[1];
    const float* w1    = (const float*)d_in[2];
    const float* b1    = (const float*)d_in[3];
    const float* w2    = (const float*)d_in[4];
    const float* b2    = (const float*)d_in[5];
    float* out = (float*)d_out;

    const long nrows = (long)in_sizes[0] / E;  // 524288
    const long nthreads = (nrows + ROWS_PER_THREAD - 1) / ROWS_PER_THREAD;
    const int grid = (int)((nthreads + BLOCK - 1) / BLOCK);

    ffq_kernel<<<grid, BLOCK>>>(x, theta, w1, b1, w2, b2, out, nrows);
}

// round 12
// speedup vs baseline: 1.2941x; 1.1991x over previous
#include <cuda_runtime.h>

// out = relu(cos(x+theta) @ W1 + b1) @ W2 + b2
// x: [B*S, 8] fp32, W1: [8,32], W2: [32,8], out: [B*S, 8] fp32
//
// R8: weights live in __constant__ memory (separate const port -> L1tex only
// sees x loads + out stores). Column-packed f32x2: multiplier = {w[j],w[j+1]}
// adjacent pairs straight from row-major layout (NO {w,w} duplication);
// multiplicand = activation broadcast {a,a} (1 MOV per 4 FFMA2).
// 4 rows/thread; accumulators o2[r][ep] = {out_2ep, out_2ep+1} are already in
// output order -> direct float4 stores.

using u64 = unsigned long long;

// Raw little-endian copies of the weight tensors, viewed as packed f32 pairs.
__constant__ u64   c_w1[8 * 16];   // [i][jp]  = {w1[i][2jp],   w1[i][2jp+1]}
__constant__ u64   c_b1[16];       // [jp]     = {b1[2jp],      b1[2jp+1]}
__constant__ u64   c_w2[32 * 4];   // [j][ep]  = {w2[j][2ep],   w2[j][2ep+1]}
__constant__ u64   c_b2[4];        // [ep]     = {b2[2ep],      b2[2ep+1]}
__constant__ float c_th[8];

__device__ __forceinline__ u64 pack2(float lo, float hi) {
    u64 r;
    asm("mov.b64 %0, {%1, %2};" : "=l"(r) : "f"(lo), "f"(hi));
    return r;
}

__device__ __forceinline__ float2 unpack2(u64 v) {
    float2 f;
    asm("mov.b64 {%0, %1}, %2;" : "=f"(f.x), "=f"(f.y) : "l"(v));
    return f;
}

__device__ __forceinline__ u64 ffma2(u64 a, u64 b, u64 c) {
    u64 d;
    asm("fma.rn.f32x2 %0, %1, %2, %3;" : "=l"(d) : "l"(a), "l"(b), "l"(c));
    return d;
}

__device__ __forceinline__ u64 relu2(u64 v) {
    float2 f = unpack2(v);
    f.x = fmaxf(f.x, 0.0f);
    f.y = fmaxf(f.y, 0.0f);
    return pack2(f.x, f.y);
}

constexpr int E = 8;
constexpr int F = 32;
constexpr int R = 4;          // rows per thread
constexpr int BLOCK = 128;

__global__ __launch_bounds__(BLOCK)
void ffq_kernel(const float* __restrict__ x,
                float* __restrict__ out,
                long nrows)
{
    const int t = threadIdx.x;
    const long row0 = ((long)blockIdx.x * BLOCK + t) * R;
    if (row0 >= nrows) return;

    // ---- Load x: 8x LDG.128 (MLP 8), fold into q = cos(x + theta) (scalar)
    const float4* xv = (const float4*)(x + row0 * E);
    float q[R][E];
#pragma unroll
    for (int r = 0; r < R; r++) {
        float4 a = xv[2 * r + 0];
        float4 b = xv[2 * r + 1];
        q[r][0] = __cosf(a.x + c_th[0]);
        q[r][1] = __cosf(a.y + c_th[1]);
        q[r][2] = __cosf(a.z + c_th[2]);
        q[r][3] = __cosf(a.w + c_th[3]);
        q[r][4] = __cosf(b.x + c_th[4]);
        q[r][5] = __cosf(b.y + c_th[5]);
        q[r][6] = __cosf(b.z + c_th[6]);
        q[r][7] = __cosf(b.w + c_th[7]);
    }

    // ---- Output accumulators: o2[r][ep] = {out[r][2ep], out[r][2ep+1]}
    u64 o2[R][E / 2];
#pragma unroll
    for (int ep = 0; ep < E / 2; ep++) {
        u64 b = c_b2[ep];
#pragma unroll
        for (int r = 0; r < R; r++) o2[r][ep] = b;
    }

    // ---- Hidden dim in groups of 8 columns (4 column-pairs)
#pragma unroll
    for (int jg = 0; jg < F / 8; jg++) {
        const int jp0 = jg * 4;          // first column-pair of this group
        const int j0  = jg * 8;          // first column of this group

        // layer 1: h[r][p] = {h[r][j0+2p], h[r][j0+2p+1]}
        u64 h[R][4];
#pragma unroll
        for (int p = 0; p < 4; p++) {
            u64 b = c_b1[jp0 + p];
#pragma unroll
            for (int r = 0; r < R; r++) h[r][p] = b;
        }
#pragma unroll
        for (int i = 0; i < E; i++) {
#pragma unroll
            for (int r = 0; r < R; r++) {
                u64 qb = pack2(q[r][i], q[r][i]);   // 1 MOV, feeds 4 FFMA2
#pragma unroll
                for (int p = 0; p < 4; p++) {
                    h[r][p] = ffma2(qb, c_w1[i * 16 + jp0 + p], h[r][p]);
                }
            }
        }

        // relu
#pragma unroll
        for (int r = 0; r < R; r++) {
#pragma unroll
            for (int p = 0; p < 4; p++) h[r][p] = relu2(h[r][p]);
        }

        // layer 2: for each column j in group, broadcast h and accumulate
#pragma unroll
        for (int jj = 0; jj < 8; jj++) {
            const int j = j0 + jj;
#pragma unroll
            for (int r = 0; r < R; r++) {
                float2 hf = unpack2(h[r][jj >> 1]);   // free (reg aliasing)
                float hv = (jj & 1) ? hf.y : hf.x;
                u64 hb = pack2(hv, hv);               // 1 MOV, feeds 4 FFMA2
#pragma unroll
                for (int ep = 0; ep < E / 2; ep++) {
                    o2[r][ep] = ffma2(hb, c_w2[j * 4 + ep], o2[r][ep]);
                }
            }
        }
    }

    // ---- Store: o2[r] is row r's 8 outputs in order -> 2x STG.128 per row
    float4* ov = (float4*)(out + row0 * E);
#pragma unroll
    for (int r = 0; r < R; r++) {
        float2 f0 = unpack2(o2[r][0]);
        float2 f1 = unpack2(o2[r][1]);
        float2 f2 = unpack2(o2[r][2]);
        float2 f3 = unpack2(o2[r][3]);
        ov[2 * r + 0] = make_float4(f0.x, f0.y, f1.x, f1.y);
        ov[2 * r + 1] = make_float4(f2.x, f2.y, f3.x, f3.y);
    }
}

extern "C" void kernel_launch(void* const* d_in, const int* in_sizes, int n_in,
                              void* d_out, int out_size)
{
    const float* x     = (const float*)d_in[0];
    const float* theta = (const float*)d_in[1];
    const float* w1    = (const float*)d_in[2];
    const float* b1    = (const float*)d_in[3];
    const float* w2    = (const float*)d_in[4];
    const float* b2    = (const float*)d_in[5];
    float* out = (float*)d_out;

    // Stage weights into __constant__ (D2D async memcpys: graph-capturable).
    // Adjacent-pair u64 views are raw little-endian copies of the row-major
    // float tensors, so plain byte copies produce the packed layouts.
    cudaMemcpyToSymbolAsync(c_w1, w1,    8 * 32 * sizeof(float), 0, cudaMemcpyDeviceToDevice, 0);
    cudaMemcpyToSymbolAsync(c_b1, b1,    32 * sizeof(float),     0, cudaMemcpyDeviceToDevice, 0);
    cudaMemcpyToSymbolAsync(c_w2, w2,    32 * 8 * sizeof(float), 0, cudaMemcpyDeviceToDevice, 0);
    cudaMemcpyToSymbolAsync(c_b2, b2,    8 * sizeof(float),      0, cudaMemcpyDeviceToDevice, 0);
    cudaMemcpyToSymbolAsync(c_th, theta, 8 * sizeof(float),      0, cudaMemcpyDeviceToDevice, 0);

    const long nrows = (long)in_sizes[0] / E;  // 524288
    const long nthreads = (nrows + R - 1) / R;
    const int grid = (int)((nthreads + BLOCK - 1) / BLOCK);

    ffq_kernel<<<grid, BLOCK>>>(x, out, nrows);
}